// round 15
// baseline (speedup 1.0000x reference)
#include <cuda_runtime.h>
#include <math.h>
#include <stdint.h>

// EnhancedFinancialGAT collapse: initial node features are uniform over nodes,
// so GAT attention (softmax weights summing to 1 per dst) aggregates identical
// messages -> each GAT layer == relu(W @ g + b). Whole net = per-item MLP.
//
// R14 -> R15: revert to R11 (cluster-4, 2 items/cluster, 16-lane row groups,
// barrier.cluster; 17.1us champion), then split the barrier into arrive/wait
// and prefetch the NEXT stage's weights into registers between them. The
// weight L2 round-trip (static addresses, sync-independent) now overlaps the
// barrier skew instead of following it.

#define IN_DIM 64
#define ACT_STRIDE 704   // per item: s0[320] | s1[256] | s2[128]

__device__ __forceinline__ uint32_t smem_u32(const void* p) {
    uint32_t a;
    asm("{ .reg .u64 t; cvta.to.shared.u64 t, %1; cvt.u32.u64 %0, t; }"
        : "=r"(a) : "l"(p));
    return a;
}
__device__ __forceinline__ uint32_t mapa_u32(uint32_t addr, uint32_t rank) {
    uint32_t r;
    asm("mapa.shared::cluster.u32 %0, %1, %2;" : "=r"(r) : "r"(addr), "r"(rank));
    return r;
}
__device__ __forceinline__ void st_peer(uint32_t addr, float v) {
    asm volatile("st.shared::cluster.f32 [%0], %1;" :: "r"(addr), "f"(v) : "memory");
}
__device__ __forceinline__ void cluster_arrive() {
    asm volatile("barrier.cluster.arrive.aligned;" ::: "memory");
}
__device__ __forceinline__ void cluster_wait() {
    asm volatile("barrier.cluster.wait.aligned;" ::: "memory");
}

// Load this thread's weight chunks for a shared-layer row (16 lanes per row).
template<int NCH>
__device__ __forceinline__ void loadw(float4* __restrict__ w,
                                      const float* __restrict__ W,
                                      int row, int l) {
    const float4* __restrict__ w4 =
        reinterpret_cast<const float4*>(W) + row * (NCH * 16);
#pragma unroll
    for (int j = 0; j < NCH; j++) w[j] = __ldg(w4 + j * 16 + l);
}

// Compute one shared-layer row (both items) from preloaded weights, store the
// relu'd outputs to all 4 CTAs. No sync inside.
template<int NCH>
__device__ __forceinline__ void compute_store(
    const float4* __restrict__ w, const float* __restrict__ bias,
    const float* __restrict__ act, int in_off, int out_off,
    int row, int l, const uint32_t* __restrict__ peer)
{
    const float4* __restrict__ ua = reinterpret_cast<const float4*>(act + in_off);
    const float4* __restrict__ ub = reinterpret_cast<const float4*>(act + ACT_STRIDE + in_off);
    float4 p = make_float4(0.f, 0.f, 0.f, 0.f);
    float4 q = make_float4(0.f, 0.f, 0.f, 0.f);
#pragma unroll
    for (int j = 0; j < NCH; j++) {
        const float4 u = ua[j * 16 + l];
        const float4 v = ub[j * 16 + l];
        p.x = fmaf(w[j].x, u.x, p.x); p.y = fmaf(w[j].y, u.y, p.y);
        p.z = fmaf(w[j].z, u.z, p.z); p.w = fmaf(w[j].w, u.w, p.w);
        q.x = fmaf(w[j].x, v.x, q.x); q.y = fmaf(w[j].y, v.y, q.y);
        q.z = fmaf(w[j].z, v.z, q.z); q.w = fmaf(w[j].w, v.w, q.w);
    }
    float rp = (p.x + p.y) + (p.z + p.w);
    float rq = (q.x + q.y) + (q.z + q.w);
#pragma unroll
    for (int o = 1; o < 16; o <<= 1) {
        rp += __shfl_xor_sync(0xffffffffu, rp, o);
        rq += __shfl_xor_sync(0xffffffffu, rq, o);
    }
    if (l == 0) {
        const float bs = __ldg(bias + row);
        const float a  = fmaxf(rp + bs, 0.f);
        const float b2 = fmaxf(rq + bs, 0.f);
#pragma unroll
        for (int r = 0; r < 4; r++) {
            st_peer(peer[r] + (uint32_t)(out_off + row) * 4, a);
            st_peer(peer[r] + (uint32_t)(ACT_STRIDE + out_off + row) * 4, b2);
        }
    }
}

// Local tail layer row (one item), 8 lanes per row.
template<int NCH>
__device__ __forceinline__ void local_layer8(
    const float* __restrict__ W, const float* __restrict__ bias,
    const float* __restrict__ vin, float* __restrict__ vout,
    int row, int l)
{
    const float4* __restrict__ w4 = reinterpret_cast<const float4*>(W) + row * (NCH * 8);
    const float4* __restrict__ u4 = reinterpret_cast<const float4*>(vin);
    float4 w[NCH];
#pragma unroll
    for (int j = 0; j < NCH; j++) w[j] = __ldg(w4 + j * 8 + l);
    float4 p = make_float4(0.f, 0.f, 0.f, 0.f);
#pragma unroll
    for (int j = 0; j < NCH; j++) {
        const float4 u = u4[j * 8 + l];
        p.x = fmaf(w[j].x, u.x, p.x); p.y = fmaf(w[j].y, u.y, p.y);
        p.z = fmaf(w[j].z, u.z, p.z); p.w = fmaf(w[j].w, u.w, p.w);
    }
    float r = (p.x + p.y) + (p.z + p.w);
#pragma unroll
    for (int o = 1; o < 8; o <<= 1) r += __shfl_xor_sync(0xffffffffu, r, o);
    if (l == 0) vout[row] = fmaxf(r + __ldg(bias + row), 0.f);
}

__global__ __launch_bounds__(1024) __cluster_dims__(4, 1, 1)
void gat_c4pf_kernel(
    const float* __restrict__ x, const int* __restrict__ company_idx,
    const float* __restrict__ W_in,  const float* __restrict__ b_in,
    const float* __restrict__ gat_W, const float* __restrict__ gat_b,
    const float* __restrict__ emb,
    const float* __restrict__ W_fuse, const float* __restrict__ b_fuse,
    const float* __restrict__ W_p1, const float* __restrict__ b_p1,
    const float* __restrict__ W_p2, const float* __restrict__ b_p2,
    const float* __restrict__ W_p3, const float* __restrict__ b_p3,
    const float* __restrict__ W_d1, const float* __restrict__ b_d1,
    const float* __restrict__ W_d2, const float* __restrict__ b_d2,
    const float* __restrict__ W_d3, const float* __restrict__ b_d3,
    float* __restrict__ out)
{
    __shared__ __align__(16) float act[2 * ACT_STRIDE];

    const int tid   = threadIdx.x;
    const int grp16 = tid >> 4;        // 0..63
    const int l16   = tid & 15;
    const int grp8  = tid >> 3;        // 0..127
    const int l8    = tid & 7;
    uint32_t rank;
    asm("mov.u32 %0, %%cluster_ctarank;" : "=r"(rank));
    const int b0   = (blockIdx.x >> 2) * 2;   // 2 items per 4-CTA cluster
    const int base = rank * 64;               // row quarter owned by this CTA
    const int myrow = base + grp16;

    uint32_t peer[4];
    {
        const uint32_t a = smem_u32(act);
#pragma unroll
        for (int r = 0; r < 4; r++) peer[r] = mapa_u32(a, r);
    }

    float4 w[5];
    // stage-0 weights load before anything else
    loadw<1>(w, W_in, myrow, l16);

    // init: x rows + emb rows for both items (each CTA local copy)
    if (tid < 128) {
        const int it = tid >> 6, c = tid & 63;
        const int bb = b0 + it;
        float* s0 = act + it * ACT_STRIDE;
        s0[c]       = __ldg(&x[bb * IN_DIM + c]);
        s0[256 + c] = __ldg(&emb[__ldg(&company_idx[bb]) * IN_DIM + c]);
    }
    __syncthreads();

    // stage 0 — W_in: 256x64, s0[0:64] -> s1
    compute_store<1>(w, b_in, act, 0, 320, myrow, l16, peer);
    cluster_arrive();
    loadw<4>(w, gat_W, myrow, l16);            // prefetch under barrier skew
    cluster_wait();
    // stage 1..3 — GAT layers (uniform-node collapse): 256x256
    compute_store<4>(w, gat_b, act, 320, 0, myrow, l16, peer);
    cluster_arrive();
    loadw<4>(w, gat_W + 65536, myrow, l16);
    cluster_wait();
    compute_store<4>(w, gat_b + 256, act, 0, 320, myrow, l16, peer);
    cluster_arrive();
    loadw<4>(w, gat_W + 131072, myrow, l16);
    cluster_wait();
    compute_store<4>(w, gat_b + 512, act, 320, 0, myrow, l16, peer);
    cluster_arrive();
    loadw<5>(w, W_fuse, myrow, l16);
    cluster_wait();
    // stage 4 — fuse: 256x320 (s0 = [gat2 | emb]) -> s1
    compute_store<5>(w, b_fuse, act, 0, 320, myrow, l16, peer);
    cluster_arrive();
    cluster_wait();

    // tail: rank -> (branch = rank>>1, item = rank&1), fully local
    const int item   = rank & 1;
    const int branch = rank >> 1;            // 0 = price, 1 = direction
    const float* W1 = branch ? W_d1 : W_p1;
    const float* c1 = branch ? b_d1 : b_p1;
    const float* W2 = branch ? W_d2 : W_p2;
    const float* c2 = branch ? b_d2 : b_p2;
    const float* W3 = branch ? W_d3 : W_p3;
    const float* c3 = branch ? b_d3 : b_p3;
    const float* fused = act + item * ACT_STRIDE + 320;

    // l1: 128x256, fused -> act[0:128] (scratch; item0 s0 is dead now)
    local_layer8<8>(W1, c1, fused, act, grp8, l8);
    __syncthreads();
    // l2: 64x128, act[0:128] -> act[576:640]
    if (grp8 < 64)
        local_layer8<4>(W2, c2, act, act + 576, grp8, l8);
    __syncthreads();

    // head: warp 0, 64-dot
    if (tid < 32) {
        const float2 wv = __ldg(&reinterpret_cast<const float2*>(W3)[tid]);
        const float2 vv = reinterpret_cast<const float2*>(act + 576)[tid];
        float r = fmaf(wv.x, vv.x, wv.y * vv.y);
#pragma unroll
        for (int o = 16; o; o >>= 1) r += __shfl_xor_sync(0xffffffffu, r, o);
        if (tid == 0) {
            const float v = r + __ldg(c3);
            const int bb = b0 + item;
            if (branch == 0) out[bb] = v;                            // price
            else             out[64 + bb] = 1.f / (1.f + expf(-v));  // direction
        }
    }
}

extern "C" void kernel_launch(void* const* d_in, const int* in_sizes, int n_in,
                              void* d_out, int out_size) {
    const float* x      = (const float*)d_in[0];
    const int*   ci     = (const int*)  d_in[1];
    const float* W_in   = (const float*)d_in[4];
    const float* b_in   = (const float*)d_in[5];
    const float* gat_W  = (const float*)d_in[6];
    const float* gat_b  = (const float*)d_in[11];
    const float* emb    = (const float*)d_in[12];
    const float* W_fuse = (const float*)d_in[13];
    const float* b_fuse = (const float*)d_in[14];
    const float* W_p1   = (const float*)d_in[15];
    const float* b_p1   = (const float*)d_in[16];
    const float* W_p2   = (const float*)d_in[17];
    const float* b_p2   = (const float*)d_in[18];
    const float* W_p3   = (const float*)d_in[19];
    const float* b_p3   = (const float*)d_in[20];
    const float* W_d1   = (const float*)d_in[21];
    const float* b_d1   = (const float*)d_in[22];
    const float* W_d2   = (const float*)d_in[23];
    const float* b_d2   = (const float*)d_in[24];
    const float* W_d3   = (const float*)d_in[25];
    const float* b_d3   = (const float*)d_in[26];

    const int B = in_sizes[0] / IN_DIM;  // 64

    // 32 clusters x 4 CTAs = 128 blocks, 2 items per cluster
    gat_c4pf_kernel<<<B * 2, 1024>>>(
        x, ci, W_in, b_in, gat_W, gat_b, emb, W_fuse, b_fuse,
        W_p1, b_p1, W_p2, b_p2, W_p3, b_p3,
        W_d1, b_d1, W_d2, b_d2, W_d3, b_d3,
        (float*)d_out);
}

// round 16
// speedup vs baseline: 1.2892x; 1.2892x over previous
#include <cuda_runtime.h>
#include <math.h>
#include <stdint.h>

// EnhancedFinancialGAT collapse: initial node features are uniform over nodes,
// so GAT attention (softmax weights summing to 1 per dst) aggregates identical
// messages -> each GAT layer == relu(W @ g + b). Whole net = per-item MLP.
//
// R15 -> R16: R11 topology (cluster-4, 2 items/cluster, barrier.cluster),
// but stages are LSU-issue-bound -> cut LSU ops: 512 threads, 16-lane groups
// each computing 2 rows (act LDS chunks shared across rows). 8 LDG + 8 LDS
// per thread per gat stage (was 12 ops/thread x 1024). Loads stay inside the
// stage so defer-blocking barriers overlap them naturally.

#define IN_DIM 64
#define ACT_STRIDE 704   // per item: s0[320] | s1[256] | s2[128]

__device__ __forceinline__ uint32_t smem_u32(const void* p) {
    uint32_t a;
    asm("{ .reg .u64 t; cvta.to.shared.u64 t, %1; cvt.u32.u64 %0, t; }"
        : "=r"(a) : "l"(p));
    return a;
}
__device__ __forceinline__ uint32_t mapa_u32(uint32_t addr, uint32_t rank) {
    uint32_t r;
    asm("mapa.shared::cluster.u32 %0, %1, %2;" : "=r"(r) : "r"(addr), "r"(rank));
    return r;
}
__device__ __forceinline__ void st_peer(uint32_t addr, float v) {
    asm volatile("st.shared::cluster.f32 [%0], %1;" :: "r"(addr), "f"(v) : "memory");
}
__device__ __forceinline__ void cluster_sync() {
    asm volatile("barrier.cluster.arrive.aligned;" ::: "memory");
    asm volatile("barrier.cluster.wait.aligned;" ::: "memory");
}

// Shared layer, 16-lane group computes rows (row0, row0+32) for both items.
// Act chunks are loaded once and reused for both rows. Results broadcast to
// all 4 CTAs by lane 0.
template<int NCH>
__device__ __forceinline__ void shared_layer2r(
    const float* __restrict__ W, const float* __restrict__ bias,
    const float* __restrict__ act, int in_off, int out_off,
    int row0, int l, const uint32_t* __restrict__ peer)
{
    const float4* __restrict__ wa = reinterpret_cast<const float4*>(W) + row0 * (NCH * 16);
    const float4* __restrict__ wb = wa + 32 * (NCH * 16);
    const float4* __restrict__ ua = reinterpret_cast<const float4*>(act + in_off);
    const float4* __restrict__ ub = reinterpret_cast<const float4*>(act + ACT_STRIDE + in_off);

    float4 p0 = make_float4(0.f,0.f,0.f,0.f), q0 = p0, p1 = p0, q1 = p0;
#pragma unroll
    for (int j = 0; j < NCH; j++) {
        const float4 w0 = __ldg(wa + j * 16 + l);
        const float4 w1 = __ldg(wb + j * 16 + l);
        const float4 u  = ua[j * 16 + l];
        const float4 v  = ub[j * 16 + l];
        p0.x = fmaf(w0.x, u.x, p0.x); p0.y = fmaf(w0.y, u.y, p0.y);
        p0.z = fmaf(w0.z, u.z, p0.z); p0.w = fmaf(w0.w, u.w, p0.w);
        q0.x = fmaf(w0.x, v.x, q0.x); q0.y = fmaf(w0.y, v.y, q0.y);
        q0.z = fmaf(w0.z, v.z, q0.z); q0.w = fmaf(w0.w, v.w, q0.w);
        p1.x = fmaf(w1.x, u.x, p1.x); p1.y = fmaf(w1.y, u.y, p1.y);
        p1.z = fmaf(w1.z, u.z, p1.z); p1.w = fmaf(w1.w, u.w, p1.w);
        q1.x = fmaf(w1.x, v.x, q1.x); q1.y = fmaf(w1.y, v.y, q1.y);
        q1.z = fmaf(w1.z, v.z, q1.z); q1.w = fmaf(w1.w, v.w, q1.w);
    }
    float rp0 = (p0.x + p0.y) + (p0.z + p0.w);
    float rq0 = (q0.x + q0.y) + (q0.z + q0.w);
    float rp1 = (p1.x + p1.y) + (p1.z + p1.w);
    float rq1 = (q1.x + q1.y) + (q1.z + q1.w);
#pragma unroll
    for (int o = 1; o < 16; o <<= 1) {
        rp0 += __shfl_xor_sync(0xffffffffu, rp0, o);
        rq0 += __shfl_xor_sync(0xffffffffu, rq0, o);
        rp1 += __shfl_xor_sync(0xffffffffu, rp1, o);
        rq1 += __shfl_xor_sync(0xffffffffu, rq1, o);
    }
    if (l == 0) {
        const float bs0 = __ldg(bias + row0);
        const float bs1 = __ldg(bias + row0 + 32);
        const float a0 = fmaxf(rp0 + bs0, 0.f);
        const float b0 = fmaxf(rq0 + bs0, 0.f);
        const float a1 = fmaxf(rp1 + bs1, 0.f);
        const float b1 = fmaxf(rq1 + bs1, 0.f);
#pragma unroll
        for (int r = 0; r < 4; r++) {
            const uint32_t pb = peer[r];
            st_peer(pb + (uint32_t)(out_off + row0) * 4, a0);
            st_peer(pb + (uint32_t)(ACT_STRIDE + out_off + row0) * 4, b0);
            st_peer(pb + (uint32_t)(out_off + row0 + 32) * 4, a1);
            st_peer(pb + (uint32_t)(ACT_STRIDE + out_off + row0 + 32) * 4, b1);
        }
    }
}

// Local tail layer, 8-lane group computes rows (row0, row0+64) of one item.
template<int NCH>
__device__ __forceinline__ void local_layer2r(
    const float* __restrict__ W, const float* __restrict__ bias,
    const float* __restrict__ vin, float* __restrict__ vout,
    int row0, int l)
{
    const float4* __restrict__ wa = reinterpret_cast<const float4*>(W) + row0 * (NCH * 8);
    const float4* __restrict__ wb = wa + 64 * (NCH * 8);
    const float4* __restrict__ u4 = reinterpret_cast<const float4*>(vin);
    float4 p0 = make_float4(0.f,0.f,0.f,0.f), p1 = p0;
#pragma unroll
    for (int j = 0; j < NCH; j++) {
        const float4 w0 = __ldg(wa + j * 8 + l);
        const float4 w1 = __ldg(wb + j * 8 + l);
        const float4 u  = u4[j * 8 + l];
        p0.x = fmaf(w0.x, u.x, p0.x); p0.y = fmaf(w0.y, u.y, p0.y);
        p0.z = fmaf(w0.z, u.z, p0.z); p0.w = fmaf(w0.w, u.w, p0.w);
        p1.x = fmaf(w1.x, u.x, p1.x); p1.y = fmaf(w1.y, u.y, p1.y);
        p1.z = fmaf(w1.z, u.z, p1.z); p1.w = fmaf(w1.w, u.w, p1.w);
    }
    float r0 = (p0.x + p0.y) + (p0.z + p0.w);
    float r1 = (p1.x + p1.y) + (p1.z + p1.w);
#pragma unroll
    for (int o = 1; o < 8; o <<= 1) {
        r0 += __shfl_xor_sync(0xffffffffu, r0, o);
        r1 += __shfl_xor_sync(0xffffffffu, r1, o);
    }
    if (l == 0) {
        vout[row0]      = fmaxf(r0 + __ldg(bias + row0), 0.f);
        vout[row0 + 64] = fmaxf(r1 + __ldg(bias + row0 + 64), 0.f);
    }
}

// Local layer, 8-lane group, single row (for the 64-row l2 stage).
template<int NCH>
__device__ __forceinline__ void local_layer1r(
    const float* __restrict__ W, const float* __restrict__ bias,
    const float* __restrict__ vin, float* __restrict__ vout,
    int row, int l)
{
    const float4* __restrict__ w4 = reinterpret_cast<const float4*>(W) + row * (NCH * 8);
    const float4* __restrict__ u4 = reinterpret_cast<const float4*>(vin);
    float4 p = make_float4(0.f,0.f,0.f,0.f);
#pragma unroll
    for (int j = 0; j < NCH; j++) {
        const float4 w = __ldg(w4 + j * 8 + l);
        const float4 u = u4[j * 8 + l];
        p.x = fmaf(w.x, u.x, p.x); p.y = fmaf(w.y, u.y, p.y);
        p.z = fmaf(w.z, u.z, p.z); p.w = fmaf(w.w, u.w, p.w);
    }
    float r = (p.x + p.y) + (p.z + p.w);
#pragma unroll
    for (int o = 1; o < 8; o <<= 1) r += __shfl_xor_sync(0xffffffffu, r, o);
    if (l == 0) vout[row] = fmaxf(r + __ldg(bias + row), 0.f);
}

__global__ __launch_bounds__(512) __cluster_dims__(4, 1, 1)
void gat_c4x512_kernel(
    const float* __restrict__ x, const int* __restrict__ company_idx,
    const float* __restrict__ W_in,  const float* __restrict__ b_in,
    const float* __restrict__ gat_W, const float* __restrict__ gat_b,
    const float* __restrict__ emb,
    const float* __restrict__ W_fuse, const float* __restrict__ b_fuse,
    const float* __restrict__ W_p1, const float* __restrict__ b_p1,
    const float* __restrict__ W_p2, const float* __restrict__ b_p2,
    const float* __restrict__ W_p3, const float* __restrict__ b_p3,
    const float* __restrict__ W_d1, const float* __restrict__ b_d1,
    const float* __restrict__ W_d2, const float* __restrict__ b_d2,
    const float* __restrict__ W_d3, const float* __restrict__ b_d3,
    float* __restrict__ out)
{
    __shared__ __align__(16) float act[2 * ACT_STRIDE];

    const int tid   = threadIdx.x;
    const int grp16 = tid >> 4;        // 0..31
    const int l16   = tid & 15;
    const int grp8  = tid >> 3;        // 0..63
    const int l8    = tid & 7;
    uint32_t rank;
    asm("mov.u32 %0, %%cluster_ctarank;" : "=r"(rank));
    const int b0    = (blockIdx.x >> 2) * 2;  // 2 items per 4-CTA cluster
    const int myrow = rank * 64 + grp16;      // first of this group's 2 rows

    uint32_t peer[4];
    {
        const uint32_t a = smem_u32(act);
#pragma unroll
        for (int r = 0; r < 4; r++) peer[r] = mapa_u32(a, r);
    }

    // init: x rows + emb rows for both items (each CTA local copy)
    if (tid < 128) {
        const int it = tid >> 6, c = tid & 63;
        const int bb = b0 + it;
        float* s0 = act + it * ACT_STRIDE;
        s0[c]       = __ldg(&x[bb * IN_DIM + c]);
        s0[256 + c] = __ldg(&emb[__ldg(&company_idx[bb]) * IN_DIM + c]);
    }
    __syncthreads();

    // stage 0 — W_in: 256x64, s0[0:64] -> s1
    shared_layer2r<1>(W_in, b_in, act, 0, 320, myrow, l16, peer);
    cluster_sync();
    // stages 1..3 — GAT layers (uniform-node collapse): 256x256
    shared_layer2r<4>(gat_W,          gat_b,       act, 320, 0,   myrow, l16, peer);
    cluster_sync();
    shared_layer2r<4>(gat_W +  65536, gat_b + 256, act, 0,   320, myrow, l16, peer);
    cluster_sync();
    shared_layer2r<4>(gat_W + 131072, gat_b + 512, act, 320, 0,   myrow, l16, peer);
    cluster_sync();
    // stage 4 — fuse: 256x320 (s0 = [gat2 | emb]) -> s1
    shared_layer2r<5>(W_fuse, b_fuse, act, 0, 320, myrow, l16, peer);
    cluster_sync();

    // tail: rank -> (branch = rank>>1, item = rank&1), fully local
    const int item   = rank & 1;
    const int branch = rank >> 1;            // 0 = price, 1 = direction
    const float* W1 = branch ? W_d1 : W_p1;
    const float* c1 = branch ? b_d1 : b_p1;
    const float* W2 = branch ? W_d2 : W_p2;
    const float* c2 = branch ? b_d2 : b_p2;
    const float* W3 = branch ? W_d3 : W_p3;
    const float* c3 = branch ? b_d3 : b_p3;
    const float* fused = act + item * ACT_STRIDE + 320;

    // l1: 128x256, fused -> act[0:128]; groups handle rows (g, g+64)
    local_layer2r<8>(W1, c1, fused, act, grp8, l8);
    __syncthreads();
    // l2: 64x128, act[0:128] -> act[576:640]; 64 groups, 1 row each
    local_layer1r<4>(W2, c2, act, act + 576, grp8, l8);
    __syncthreads();

    // head: warp 0, 64-dot
    if (tid < 32) {
        const float2 wv = __ldg(&reinterpret_cast<const float2*>(W3)[tid]);
        const float2 vv = reinterpret_cast<const float2*>(act + 576)[tid];
        float r = fmaf(wv.x, vv.x, wv.y * vv.y);
#pragma unroll
        for (int o = 16; o; o >>= 1) r += __shfl_xor_sync(0xffffffffu, r, o);
        if (tid == 0) {
            const float v = r + __ldg(c3);
            const int bb = b0 + item;
            if (branch == 0) out[bb] = v;                            // price
            else             out[64 + bb] = 1.f / (1.f + expf(-v));  // direction
        }
    }
}

extern "C" void kernel_launch(void* const* d_in, const int* in_sizes, int n_in,
                              void* d_out, int out_size) {
    const float* x      = (const float*)d_in[0];
    const int*   ci     = (const int*)  d_in[1];
    const float* W_in   = (const float*)d_in[4];
    const float* b_in   = (const float*)d_in[5];
    const float* gat_W  = (const float*)d_in[6];
    const float* gat_b  = (const float*)d_in[11];
    const float* emb    = (const float*)d_in[12];
    const float* W_fuse = (const float*)d_in[13];
    const float* b_fuse = (const float*)d_in[14];
    const float* W_p1   = (const float*)d_in[15];
    const float* b_p1   = (const float*)d_in[16];
    const float* W_p2   = (const float*)d_in[17];
    const float* b_p2   = (const float*)d_in[18];
    const float* W_p3   = (const float*)d_in[19];
    const float* b_p3   = (const float*)d_in[20];
    const float* W_d1   = (const float*)d_in[21];
    const float* b_d1   = (const float*)d_in[22];
    const float* W_d2   = (const float*)d_in[23];
    const float* b_d2   = (const float*)d_in[24];
    const float* W_d3   = (const float*)d_in[25];
    const float* b_d3   = (const float*)d_in[26];

    const int B = in_sizes[0] / IN_DIM;  // 64

    // 32 clusters x 4 CTAs = 128 blocks, 2 items per cluster
    gat_c4x512_kernel<<<B * 2, 512>>>(
        x, ci, W_in, b_in, gat_W, gat_b, emb, W_fuse, b_fuse,
        W_p1, b_p1, W_p2, b_p2, W_p3, b_p3,
        W_d1, b_d1, W_d2, b_d2, W_d3, b_d3,
        (float*)d_out);
}